// round 5
// baseline (speedup 1.0000x reference)
#include <cuda_runtime.h>
#include <cuda_bf16.h>
#include <cstdint>

// Fused adapter: out = x + 0.1f * ( relu( LN(x) @ Wd + bd ) @ Wu + bu )
// x: [32768, 768] fp32.  Wd: [768,16], Wu: [16,768].
//
// R5: 384-thread blocks (12 warps, +50% issue capacity vs R4) with finer
// weight sharding so total register footprint stays flat:
//   - up-proj: thread owns cols d = t and t+384  (wu2[2][8] = 32 regs)
//   - down-proj: warp (c,g) = (k-chunk of 8, d-range of 128); lane owns
//     4 d-values x 4 k-pairs (wd2[4][4] = 32 regs)
// Convergent keep/send butterfly reductions as R4.

#define D_MODEL  768
#define NROWS    32768
#define NTHREADS 384
#define NWARPS   12
#define RB       8              // rows per batch
#define GRID     152            // persistent: one block per SM
#define NBATCH   (NROWS / RB)   // 4096

typedef unsigned long long u64;

__device__ __forceinline__ u64 pk2(float x, float y) {
    u64 r; asm("mov.b64 %0,{%1,%2};" : "=l"(r) : "f"(x), "f"(y)); return r;
}
__device__ __forceinline__ void upk2(u64 v, float& x, float& y) {
    asm("mov.b64 {%0,%1},%2;" : "=f"(x), "=f"(y) : "l"(v));
}
__device__ __forceinline__ u64 ffma2(u64 a, u64 b, u64 c) {
    u64 r; asm("fma.rn.f32x2 %0,%1,%2,%3;" : "=l"(r) : "l"(a), "l"(b), "l"(c)); return r;
}
__device__ __forceinline__ float shx(float v, int off) {
    return __shfl_xor_sync(0xFFFFFFFFu, v, off);
}
// Convergent pair-combine: ONE unconditional shuffle, values selected first.
__device__ __forceinline__ float bfly(float a, float b, bool hi, int off) {
    const float keep = hi ? b : a;
    const float send = hi ? a : b;
    return keep + shx(send, off);
}

__global__ __launch_bounds__(NTHREADS, 1)
void adapter_fused_kernel(const float* __restrict__ x,
                          const float* __restrict__ ln_g,
                          const float* __restrict__ ln_b,
                          const float* __restrict__ wd,   // [768][16]
                          const float* __restrict__ bd,   // [16]
                          const float* __restrict__ wu,   // [16][768]
                          const float* __restrict__ bu,   // [768]
                          float* __restrict__ out)
{
    __shared__ __align__(16) float  xn_s[RB * D_MODEL];     // 24 KB
    __shared__ __align__(16) float  red_s[RB * 32];         // per row: 12x(s,q), padded
    __shared__ __align__(16) float2 stats_s[RB];            // per row (mean, rstd)
    __shared__ __align__(16) float  dpart[RB * 16 * 8];     // row x 16k x (6 g + 2 pad)
    __shared__ __align__(16) float  down_f[RB * 16];        // row x 16 relu'd acts
    __shared__ __align__(16) float  bd_s[16];

    const int t    = threadIdx.x;
    const int lane = t & 31;
    const int w    = t >> 5;       // warp 0..11
    const int c    = w & 1;        // k-chunk: k in [8c, 8c+8)
    const int g    = w >> 1;       // d-group: d in [128g, 128g+128)

    if (t < 16) bd_s[t] = bd[t];

    // ---- register-resident weights (once per block) ----
    // down: lane owns d = 128g + 32i + lane (i<4); 4 k-pairs of chunk c
    u64 wd2[4][4];
#pragma unroll
    for (int i = 0; i < 4; i++) {
        const int d = 128 * g + 32 * i + lane;
#pragma unroll
        for (int p = 0; p < 4; p++) {
            const float2 v = *reinterpret_cast<const float2*>(wd + d * 16 + 8 * c + 2 * p);
            wd2[i][p] = pk2(v.x, v.y);
        }
    }
    // up: thread owns cols d = t and t + 384; all 8 k-pairs each
    u64 wu2[2][8];
    float gj[2], bj[2], buj[2];
#pragma unroll
    for (int j = 0; j < 2; j++) {
        const int d = t + 384 * j;
        gj[j]  = ln_g[d];
        bj[j]  = ln_b[d];
        buj[j] = bu[d];
#pragma unroll
        for (int p = 0; p < 8; p++)
            wu2[j][p] = pk2(wu[(2 * p) * D_MODEL + d], wu[(2 * p + 1) * D_MODEL + d]);
    }

    const bool hi16 = (lane & 16) != 0;
    const bool hi8  = (lane & 8)  != 0;
    const bool hi4  = (lane & 4)  != 0;

    // ---- batch loop (persistent, grid-stride over 8-row batches) ----
    int b = blockIdx.x;
    float xc[RB][2];
    {
        const int rbase = b * RB;
#pragma unroll
        for (int r = 0; r < RB; r++)
#pragma unroll
            for (int j = 0; j < 2; j++)
                xc[r][j] = x[(rbase + r) * D_MODEL + t + 384 * j];
    }

    while (b < NBATCH) {
        const int rbase = b * RB;
        const int nb    = b + GRID;

        // -- LN partial stats: keep/send split (1 SHFL) + 4-SHFL tree --
#pragma unroll
        for (int r = 0; r < RB; r++) {
            float s = xc[r][0] + xc[r][1];
            float q = fmaf(xc[r][0], xc[r][0], xc[r][1] * xc[r][1]);
            float m = bfly(s, q, hi16, 16);   // lanes 0-15 carry s, 16-31 carry q
            m += shx(m, 8); m += shx(m, 4); m += shx(m, 2); m += shx(m, 1);
            if ((lane & 15) == 0)
                red_s[r * 32 + 2 * w + (lane >> 4)] = m;   // [s, q] per warp
        }
        __syncthreads();                                    // b1

        // -- finalize stats: warp w (<8) handles row w; 24 partials, pad 0 --
        if (w < RB) {
            float m = (lane < 2 * NWARPS) ? red_s[w * 32 + lane] : 0.0f;
            // parity-preserving xor tree: even lanes sum s, odd sum q
            m += shx(m, 16); m += shx(m, 8); m += shx(m, 4); m += shx(m, 2);
            const float other = shx(m, 1);   // lane0: m=s_tot, other=q_tot
            if (lane == 0) {
                const float mean = m * (1.0f / D_MODEL);
                const float var  = other * (1.0f / D_MODEL) - mean * mean;
                stats_s[w] = make_float2(mean, rsqrtf(var + 1e-5f));
            }
        }
        __syncthreads();                                    // b2

        // -- normalize, stage xn --
#pragma unroll
        for (int r = 0; r < RB; r++) {
            const float2 st = stats_s[r];
#pragma unroll
            for (int j = 0; j < 2; j++)
                xn_s[r * D_MODEL + t + 384 * j] = (xc[r][j] - st.x) * st.y * gj[j] + bj[j];
        }
        __syncthreads();                                    // b3

        // -- down-proj: warp (g, c); 8 k-values, 9-SHFL convergent butterfly --
#pragma unroll
        for (int r = 0; r < RB; r++) {
            u64 a0 = 0ull, a1 = 0ull, a2 = 0ull, a3 = 0ull;
            const float* xr = xn_s + r * D_MODEL + 128 * g + lane;
#pragma unroll
            for (int i = 0; i < 4; i++) {
                const float xs = xr[32 * i];
                const u64 xx = pk2(xs, xs);
                a0 = ffma2(xx, wd2[i][0], a0);
                a1 = ffma2(xx, wd2[i][1], a1);
                a2 = ffma2(xx, wd2[i][2], a2);
                a3 = ffma2(xx, wd2[i][3], a3);
            }
            float v0, v1, v2, v3, v4, v5, v6, v7;
            upk2(a0, v0, v1); upk2(a1, v2, v3); upk2(a2, v4, v5); upk2(a3, v6, v7);
            const float w0 = bfly(v0, v4, hi16, 16);
            const float w1 = bfly(v1, v5, hi16, 16);
            const float w2 = bfly(v2, v6, hi16, 16);
            const float w3 = bfly(v3, v7, hi16, 16);
            const float u0 = bfly(w0, w2, hi8, 8);
            const float u1 = bfly(w1, w3, hi8, 8);
            float z = bfly(u0, u1, hi4, 4);
            z += shx(z, 2);
            z += shx(z, 1);
            // lane 4j holds the full d-group sum for k = 8c + j
            if ((lane & 3) == 0)
                dpart[(r * 16 + 8 * c + (lane >> 2)) * 8 + g] = z;
        }
        __syncthreads();                                    // b4

        // -- combine 6 d-groups + bias + relu: warp w (<8) handles row w --
        if (w < RB && lane < 16) {
            const int base = (w * 16 + lane) * 8;
            const float4 p4 = *reinterpret_cast<const float4*>(dpart + base);
            const float sum = ((p4.x + p4.y) + (p4.z + p4.w))
                            + (dpart[base + 4] + dpart[base + 5]);
            down_f[w * 16 + lane] = fmaxf(sum + bd_s[lane], 0.0f);
        }
        __syncthreads();                                    // b5

        // -- up-proj + scale + residual + next-batch prefetch --
#pragma unroll
        for (int r = 0; r < RB; r++) {
            const float4 d0 = reinterpret_cast<const float4*>(down_f)[r * 4 + 0];
            const float4 d1 = reinterpret_cast<const float4*>(down_f)[r * 4 + 1];
            const float4 d2 = reinterpret_cast<const float4*>(down_f)[r * 4 + 2];
            const float4 d3 = reinterpret_cast<const float4*>(down_f)[r * 4 + 3];
            u64 dn[8];
            dn[0] = pk2(d0.x, d0.y); dn[1] = pk2(d0.z, d0.w);
            dn[2] = pk2(d1.x, d1.y); dn[3] = pk2(d1.z, d1.w);
            dn[4] = pk2(d2.x, d2.y); dn[5] = pk2(d2.z, d2.w);
            dn[6] = pk2(d3.x, d3.y); dn[7] = pk2(d3.z, d3.w);
#pragma unroll
            for (int j = 0; j < 2; j++) {
                u64 u0 = 0ull, u1 = 0ull;
#pragma unroll
                for (int p = 0; p < 8; p += 2) {
                    u0 = ffma2(dn[p],     wu2[j][p],     u0);
                    u1 = ffma2(dn[p + 1], wu2[j][p + 1], u1);
                }
                float f0, f1, f2, f3;
                upk2(u0, f0, f1); upk2(u1, f2, f3);
                const float up = (f0 + f1) + (f2 + f3);
                out[(rbase + r) * D_MODEL + t + 384 * j] = fmaf(0.1f, up + buj[j], xc[r][j]);
            }
            if (nb < NBATCH) {
#pragma unroll
                for (int j = 0; j < 2; j++)
                    xc[r][j] = x[(nb * RB + r) * D_MODEL + t + 384 * j];
            }
        }
        // no trailing barrier: every cross-iteration smem hazard is ordered
        // by the next iteration's b1..b5 (writers sit behind a barrier that
        // no warp can pass until all readers have left this phase)
        b = nb;
    }
}

extern "C" void kernel_launch(void* const* d_in, const int* in_sizes, int n_in,
                              void* d_out, int out_size)
{
    const float* x    = (const float*)d_in[0];
    const float* ln_g = (const float*)d_in[1];
    const float* ln_b = (const float*)d_in[2];
    const float* wd   = (const float*)d_in[3];
    const float* bd   = (const float*)d_in[4];
    const float* wu   = (const float*)d_in[5];
    const float* bu   = (const float*)d_in[6];
    float* out = (float*)d_out;

    adapter_fused_kernel<<<GRID, NTHREADS>>>(x, ln_g, ln_b, wd, bd, wu, bu, out);
}

// round 6
// speedup vs baseline: 1.4294x; 1.4294x over previous
#include <cuda_runtime.h>
#include <cuda_bf16.h>
#include <cstdint>

// Fused adapter: out = x + 0.1f * ( relu( LN(x) @ Wd + bd ) @ Wu + bu )
// x: [32768, 768] fp32.  Wd: [768,16], Wu: [16,768].
//
// R6 (base = R4, 256 thr / 8 warps): LN folded into down-proj.
//   down_k = rstd*( dot(x, gw_k) - mean*G_k ) + C_k + bd_k,  gw = gamma .* Wd
// G_k, C_k precomputed per block (init butterflies + smem atomics, once).
// Down-proj consumes RAW x from smem -> normalize pass and 2 of 5 barriers
// are gone (3 barriers/batch). Stats finalize is merged into the combine
// phase via broadcast LDS of per-warp partials.

#define D_MODEL  768
#define NROWS    32768
#define NTHREADS 256
#define RB       8              // rows per batch
#define GRID     152            // persistent: one block per SM
#define NBATCH   (NROWS / RB)   // 4096

typedef unsigned long long u64;

__device__ __forceinline__ u64 pk2(float x, float y) {
    u64 r; asm("mov.b64 %0,{%1,%2};" : "=l"(r) : "f"(x), "f"(y)); return r;
}
__device__ __forceinline__ void upk2(u64 v, float& x, float& y) {
    asm("mov.b64 {%0,%1},%2;" : "=f"(x), "=f"(y) : "l"(v));
}
__device__ __forceinline__ u64 ffma2(u64 a, u64 b, u64 c) {
    u64 r; asm("fma.rn.f32x2 %0,%1,%2,%3;" : "=l"(r) : "l"(a), "l"(b), "l"(c)); return r;
}
__device__ __forceinline__ float shx(float v, int off) {
    return __shfl_xor_sync(0xFFFFFFFFu, v, off);
}
// Convergent pair-combine: ONE unconditional shuffle, operands selected first.
__device__ __forceinline__ float bfly(float a, float b, bool hi, int off) {
    const float keep = hi ? b : a;
    const float send = hi ? a : b;
    return keep + shx(send, off);
}

__global__ __launch_bounds__(NTHREADS, 1)
void adapter_fused_kernel(const float* __restrict__ x,
                          const float* __restrict__ ln_g,
                          const float* __restrict__ ln_b,
                          const float* __restrict__ wd,   // [768][16]
                          const float* __restrict__ bd,   // [16]
                          const float* __restrict__ wu,   // [16][768]
                          const float* __restrict__ bu,   // [768]
                          float* __restrict__ out)
{
    __shared__ __align__(16) float x_s[RB * D_MODEL];    // raw x rows, 24 KB
    __shared__ __align__(16) float red_s[RB * 16];       // per (row, warp): s,q
    __shared__ __align__(16) float dpart[RB * 16 * 4];   // row x 16 k x 4 d-groups
    __shared__ __align__(16) float down_f[RB * 16];      // row x 16 relu'd acts
    __shared__ __align__(16) float G_s[16];              // sum_d gamma[d]*Wd[d][k]
    __shared__ __align__(16) float Cb_s[16];             // sum_d beta[d]*Wd[d][k] + bd[k]

    const int t    = threadIdx.x;
    const int lane = t & 31;
    const int w    = t >> 5;       // warp 0..7
    const int c    = w & 1;        // k-chunk: k in [8c, 8c+8)
    const int g    = w >> 1;       // d-group: d in [192g, 192g+192)

    const bool hi16 = (lane & 16) != 0;
    const bool hi8  = (lane & 8)  != 0;
    const bool hi4  = (lane & 4)  != 0;
    const bool hi2  = (lane & 2)  != 0;

    // ================= init: G_k, Cb_k (once per block) =================
    if (t < 16) { G_s[t] = 0.0f; Cb_s[t] = bd[t]; }
    __syncthreads();
    {
        float pg[16], pb[16];
#pragma unroll
        for (int k = 0; k < 16; k++) { pg[k] = 0.0f; pb[k] = 0.0f; }
#pragma unroll
        for (int j = 0; j < 3; j++) {
            const int d = t + 256 * j;
            const float gd = ln_g[d], bdv = ln_b[d];
#pragma unroll
            for (int k = 0; k < 16; k++) {
                const float wv = wd[d * 16 + k];
                pg[k] = fmaf(gd,  wv, pg[k]);
                pb[k] = fmaf(bdv, wv, pb[k]);
            }
        }
        // two 16-value convergent butterflies; k lands at lane 2k
#pragma unroll
        for (int which = 0; which < 2; which++) {
            float* v = which ? pb : pg;
            float a8[8], b4[4], c2[2];
#pragma unroll
            for (int j = 0; j < 8; j++) a8[j] = bfly(v[j], v[j + 8], hi16, 16);
#pragma unroll
            for (int j = 0; j < 4; j++) b4[j] = bfly(a8[j], a8[j + 4], hi8, 8);
#pragma unroll
            for (int j = 0; j < 2; j++) c2[j] = bfly(b4[j], b4[j + 2], hi4, 4);
            float z = bfly(c2[0], c2[1], hi2, 2);
            z += shx(z, 1);
            if (!(lane & 1)) {
                if (which) atomicAdd(&Cb_s[lane >> 1], z);
                else       atomicAdd(&G_s[lane >> 1], z);
            }
        }
    }

    // ---- register-resident weights ----
    // down (gamma-folded): lane owns d = 192g + 32i + lane (i<6), k-chunk c
    u64 gw2[6][4];
#pragma unroll
    for (int i = 0; i < 6; i++) {
        const int d = 192 * g + 32 * i + lane;
        const float gd = ln_g[d];
#pragma unroll
        for (int p = 0; p < 4; p++) {
            const float2 v = *reinterpret_cast<const float2*>(wd + d * 16 + 8 * c + 2 * p);
            gw2[i][p] = pk2(gd * v.x, gd * v.y);
        }
    }
    // up: thread owns cols d = t + 256j (j<3); all 8 k-pairs
    u64 wu2[3][8];
    float buj[3];
#pragma unroll
    for (int j = 0; j < 3; j++) {
        const int d = t + 256 * j;
        buj[j] = bu[d];
#pragma unroll
        for (int p = 0; p < 8; p++)
            wu2[j][p] = pk2(wu[(2 * p) * D_MODEL + d], wu[(2 * p + 1) * D_MODEL + d]);
    }
    __syncthreads();   // G_s/Cb_s atomics complete before main loop

    // ================= batch loop =================
    int b = blockIdx.x;
    float xc[RB][3];
    {
        const int rbase = b * RB;
#pragma unroll
        for (int r = 0; r < RB; r++)
#pragma unroll
            for (int j = 0; j < 3; j++)
                xc[r][j] = x[(rbase + r) * D_MODEL + t + 256 * j];
    }

    while (b < NBATCH) {
        const int rbase = b * RB;
        const int nb    = b + GRID;

        // -- Phase A: stage raw x to smem + LN partial stats --
#pragma unroll
        for (int r = 0; r < RB; r++) {
            x_s[r * D_MODEL + t]       = xc[r][0];
            x_s[r * D_MODEL + t + 256] = xc[r][1];
            x_s[r * D_MODEL + t + 512] = xc[r][2];
            float s = (xc[r][0] + xc[r][1]) + xc[r][2];
            float q = fmaf(xc[r][0], xc[r][0], fmaf(xc[r][1], xc[r][1], xc[r][2] * xc[r][2]));
            float m = bfly(s, q, hi16, 16);   // lanes 0-15: s, 16-31: q
            m += shx(m, 8); m += shx(m, 4); m += shx(m, 2); m += shx(m, 1);
            if ((lane & 15) == 0)
                red_s[r * 16 + 2 * w + (lane >> 4)] = m;   // [s, q] per warp
        }
        __syncthreads();                                    // b1

        // -- Phase B: down-proj on RAW x; warp (g,c); 9-SHFL butterfly --
#pragma unroll
        for (int r = 0; r < RB; r++) {
            u64 a0 = 0ull, a1 = 0ull, a2 = 0ull, a3 = 0ull;
            const float* xr = x_s + r * D_MODEL + 192 * g + lane;
#pragma unroll
            for (int i = 0; i < 6; i++) {
                const float xs = xr[32 * i];
                const u64 xx = pk2(xs, xs);
                a0 = ffma2(xx, gw2[i][0], a0);
                a1 = ffma2(xx, gw2[i][1], a1);
                a2 = ffma2(xx, gw2[i][2], a2);
                a3 = ffma2(xx, gw2[i][3], a3);
            }
            float v0, v1, v2, v3, v4, v5, v6, v7;
            upk2(a0, v0, v1); upk2(a1, v2, v3); upk2(a2, v4, v5); upk2(a3, v6, v7);
            const float w0 = bfly(v0, v4, hi16, 16);
            const float w1 = bfly(v1, v5, hi16, 16);
            const float w2 = bfly(v2, v6, hi16, 16);
            const float w3 = bfly(v3, v7, hi16, 16);
            const float u0 = bfly(w0, w2, hi8, 8);
            const float u1 = bfly(w1, w3, hi8, 8);
            float z = bfly(u0, u1, hi4, 4);
            z += shx(z, 2);
            z += shx(z, 1);
            if ((lane & 3) == 0)
                dpart[(r * 16 + 8 * c + (lane >> 2)) * 4 + g] = z;
        }
        __syncthreads();                                    // b2

        // -- Phase C: warp w = row w; finalize stats + combine + relu --
        {
            const float4* rp = reinterpret_cast<const float4*>(red_s + w * 16);
            const float4 f0 = rp[0], f1 = rp[1], f2 = rp[2], f3 = rp[3];
            const float s = ((f0.x + f0.z) + (f1.x + f1.z)) + ((f2.x + f2.z) + (f3.x + f3.z));
            const float q = ((f0.y + f0.w) + (f1.y + f1.w)) + ((f2.y + f2.w) + (f3.y + f3.w));
            const float mean = s * (1.0f / D_MODEL);
            const float var  = q * (1.0f / D_MODEL) - mean * mean;
            const float rstd = rsqrtf(var + 1e-5f);
            if (lane < 16) {
                const float4 p4 = reinterpret_cast<const float4*>(dpart)[w * 16 + lane];
                const float P = (p4.x + p4.y) + (p4.z + p4.w);
                const float dv = rstd * (P - mean * G_s[lane]) + Cb_s[lane];
                down_f[w * 16 + lane] = fmaxf(dv, 0.0f);
            }
        }
        __syncthreads();                                    // b3

        // -- Phase D: up-proj + scale + residual + prefetch next batch --
#pragma unroll
        for (int r = 0; r < RB; r++) {
            const float4 d0 = reinterpret_cast<const float4*>(down_f)[r * 4 + 0];
            const float4 d1 = reinterpret_cast<const float4*>(down_f)[r * 4 + 1];
            const float4 d2 = reinterpret_cast<const float4*>(down_f)[r * 4 + 2];
            const float4 d3 = reinterpret_cast<const float4*>(down_f)[r * 4 + 3];
            u64 dn[8];
            dn[0] = pk2(d0.x, d0.y); dn[1] = pk2(d0.z, d0.w);
            dn[2] = pk2(d1.x, d1.y); dn[3] = pk2(d1.z, d1.w);
            dn[4] = pk2(d2.x, d2.y); dn[5] = pk2(d2.z, d2.w);
            dn[6] = pk2(d3.x, d3.y); dn[7] = pk2(d3.z, d3.w);
#pragma unroll
            for (int j = 0; j < 3; j++) {
                u64 u0 = 0ull, u1 = 0ull;
#pragma unroll
                for (int p = 0; p < 8; p += 2) {
                    u0 = ffma2(dn[p],     wu2[j][p],     u0);
                    u1 = ffma2(dn[p + 1], wu2[j][p + 1], u1);
                }
                float f0, f1, f2, f3;
                upk2(u0, f0, f1); upk2(u1, f2, f3);
                const float up = (f0 + f1) + (f2 + f3);
                out[(rbase + r) * D_MODEL + t + 256 * j] = fmaf(0.1f, up + buj[j], xc[r][j]);
            }
            if (nb < NBATCH) {
#pragma unroll
                for (int j = 0; j < 3; j++)
                    xc[r][j] = x[(nb * RB + r) * D_MODEL + t + 256 * j];
            }
        }
        // no trailing barrier: D reads only down_f + registers; the next
        // iteration's writes to x_s/red_s (A) don't conflict, and every
        // other hazard is ordered by b1/b2/b3 of the next iteration.
        b = nb;
    }
}

extern "C" void kernel_launch(void* const* d_in, const int* in_sizes, int n_in,
                              void* d_out, int out_size)
{
    const float* x    = (const float*)d_in[0];
    const float* ln_g = (const float*)d_in[1];
    const float* ln_b = (const float*)d_in[2];
    const float* wd   = (const float*)d_in[3];
    const float* bd   = (const float*)d_in[4];
    const float* wu   = (const float*)d_in[5];
    const float* bu   = (const float*)d_in[6];
    float* out = (float*)d_out;

    adapter_fused_kernel<<<GRID, NTHREADS>>>(x, ln_g, ln_b, wd, bd, wu, bu, out);
}

// round 8
// speedup vs baseline: 2.0949x; 1.4656x over previous
#include <cuda_runtime.h>
#include <cuda_bf16.h>
#include <cstdint>

// Fused adapter: out = x + 0.1f * ( relu( LN(x) @ Wd + bd ) @ Wu + bu )
// x: [32768, 768] fp32.  Wd: [768,16], Wu: [16,768].
//
// R7: warp-specialized pipeline. 512 threads/block, 1 block/SM, persistent.
//   warps 0-7  (down): x -> smem, LN stats, folded down-proj -> down_f[buf]
//   warps 8-15 (up)  : up-proj + residual (global re-read, L2-hot) + store
// Producer/consumer over a 2-deep down_f ring with named barriers
// (bar.arrive by producer, bar.sync by consumer, count 512).
// LN folded into down-proj as R6:
//   down_k = rstd*( dot(x, gamma.*Wd_k) - mean*G_k ) + C_k + bd_k

#define D_MODEL  768
#define NROWS    32768
#define NTHREADS 512
#define RB       8
#define GRID     152
#define NBATCH   (NROWS / RB)   // 4096

// named barrier ids
#define BID_FULL0   2
#define BID_EMPTY0  4
#define BID_DOWN_A  6
#define BID_DOWN_B  7

#define BAR_SYNC(id, n)   asm volatile("bar.sync %0, %1;"   :: "r"(id), "r"(n) : "memory")
#define BAR_ARRIVE(id, n) asm volatile("bar.arrive %0, %1;" :: "r"(id), "r"(n) : "memory")

typedef unsigned long long u64;

__device__ __forceinline__ u64 pk2(float x, float y) {
    u64 r; asm("mov.b64 %0,{%1,%2};" : "=l"(r) : "f"(x), "f"(y)); return r;
}
__device__ __forceinline__ void upk2(u64 v, float& x, float& y) {
    asm("mov.b64 {%0,%1},%2;" : "=f"(x), "=f"(y) : "l"(v));
}
__device__ __forceinline__ u64 ffma2(u64 a, u64 b, u64 c) {
    u64 r; asm("fma.rn.f32x2 %0,%1,%2,%3;" : "=l"(r) : "l"(a), "l"(b), "l"(c)); return r;
}
__device__ __forceinline__ float shx(float v, int off) {
    return __shfl_xor_sync(0xFFFFFFFFu, v, off);
}
// Convergent pair-combine: ONE unconditional shuffle, operands selected first.
__device__ __forceinline__ float bfly(float a, float b, bool hi, int off) {
    const float keep = hi ? b : a;
    const float send = hi ? a : b;
    return keep + shx(send, off);
}

__global__ __launch_bounds__(NTHREADS, 1)
void adapter_fused_kernel(const float* __restrict__ x,
                          const float* __restrict__ ln_g,
                          const float* __restrict__ ln_b,
                          const float* __restrict__ wd,   // [768][16]
                          const float* __restrict__ bd,   // [16]
                          const float* __restrict__ wu,   // [16][768]
                          const float* __restrict__ bu,   // [768]
                          float* __restrict__ out)
{
    __shared__ __align__(16) float x_s[RB * D_MODEL];      // raw x (down-internal)
    __shared__ __align__(16) float red_s[RB * 16];         // per (row, warp): s,q
    __shared__ __align__(16) float dpart[RB * 16 * 4];     // row x 16k x 4 d-groups
    __shared__ __align__(16) float down_f[2][RB * 16];     // 2-deep ring
    __shared__ __align__(16) float G_s[16];                // sum gamma*Wd
    __shared__ __align__(16) float Cb_s[16];               // sum beta*Wd + bd

    const int t    = threadIdx.x;
    const int lane = t & 31;

    if (t < 256) {
        // ======================= DOWN role (warps 0-7) =======================
        const int w = t >> 5;       // 0..7
        const int c = w & 1;        // k-chunk: k in [8c, 8c+8)
        const int g = w >> 1;       // d-group: d in [192g, 192g+192)
        const bool hi16 = (lane & 16) != 0;
        const bool hi8  = (lane & 8)  != 0;
        const bool hi4  = (lane & 4)  != 0;
        const bool hi2  = (lane & 2)  != 0;

        // ---- init G_k, Cb_k ----
        if (t < 16) { G_s[t] = 0.0f; Cb_s[t] = bd[t]; }
        BAR_SYNC(BID_DOWN_A, 256);
        {
            float pg[16], pb[16];
#pragma unroll
            for (int k = 0; k < 16; k++) { pg[k] = 0.0f; pb[k] = 0.0f; }
#pragma unroll
            for (int j = 0; j < 3; j++) {
                const int d = t + 256 * j;
                const float gd = ln_g[d], bdv = ln_b[d];
#pragma unroll
                for (int k = 0; k < 16; k++) {
                    const float wv = wd[d * 16 + k];
                    pg[k] = fmaf(gd,  wv, pg[k]);
                    pb[k] = fmaf(bdv, wv, pb[k]);
                }
            }
#pragma unroll
            for (int which = 0; which < 2; which++) {
                float* v = which ? pb : pg;
                float a8[8], b4[4], c2[2];
#pragma unroll
                for (int j = 0; j < 8; j++) a8[j] = bfly(v[j], v[j + 8], hi16, 16);
#pragma unroll
                for (int j = 0; j < 4; j++) b4[j] = bfly(a8[j], a8[j + 4], hi8, 8);
#pragma unroll
                for (int j = 0; j < 2; j++) c2[j] = bfly(b4[j], b4[j + 2], hi4, 4);
                float z = bfly(c2[0], c2[1], hi2, 2);
                z += shx(z, 1);
                if (!(lane & 1)) {
                    if (which) atomicAdd(&Cb_s[lane >> 1], z);
                    else       atomicAdd(&G_s[lane >> 1], z);
                }
            }
        }
        // gamma-folded down weights: lane owns d = 192g + 32i + lane (i<6)
        u64 gw2[6][4];
#pragma unroll
        for (int i = 0; i < 6; i++) {
            const int d = 192 * g + 32 * i + lane;
            const float gd = ln_g[d];
#pragma unroll
            for (int p = 0; p < 4; p++) {
                const float2 v = *reinterpret_cast<const float2*>(wd + d * 16 + 8 * c + 2 * p);
                gw2[i][p] = pk2(gd * v.x, gd * v.y);
            }
        }
        BAR_SYNC(BID_DOWN_A, 256);   // G_s/Cb_s atomics complete

        int b = blockIdx.x, iter = 0;
        float xc[RB][3];
        {
            const int rbase = b * RB;
#pragma unroll
            for (int r = 0; r < RB; r++)
#pragma unroll
                for (int j = 0; j < 3; j++)
                    xc[r][j] = x[(rbase + r) * D_MODEL + t + 256 * j];
        }

        while (b < NBATCH) {
            const int buf = iter & 1;
            const int nb  = b + GRID;

            // -- A: stage raw x + LN partial stats --
#pragma unroll
            for (int r = 0; r < RB; r++) {
                x_s[r * D_MODEL + t]       = xc[r][0];
                x_s[r * D_MODEL + t + 256] = xc[r][1];
                x_s[r * D_MODEL + t + 512] = xc[r][2];
                float s = (xc[r][0] + xc[r][1]) + xc[r][2];
                float q = fmaf(xc[r][0], xc[r][0],
                          fmaf(xc[r][1], xc[r][1], xc[r][2] * xc[r][2]));
                float m = bfly(s, q, hi16, 16);
                m += shx(m, 8); m += shx(m, 4); m += shx(m, 2); m += shx(m, 1);
                if ((lane & 15) == 0)
                    red_s[r * 16 + 2 * w + (lane >> 4)] = m;
            }
            BAR_SYNC(BID_DOWN_A, 256);

            // prefetch next batch (xc regs are free; DRAM latency hidden by B/C)
            if (nb < NBATCH) {
#pragma unroll
                for (int r = 0; r < RB; r++)
#pragma unroll
                    for (int j = 0; j < 3; j++)
                        xc[r][j] = x[(nb * RB + r) * D_MODEL + t + 256 * j];
            }

            // -- B: folded down-proj on raw x; 9-SHFL butterfly --
#pragma unroll
            for (int r = 0; r < RB; r++) {
                u64 a0 = 0ull, a1 = 0ull, a2 = 0ull, a3 = 0ull;
                const float* xr = x_s + r * D_MODEL + 192 * g + lane;
#pragma unroll
                for (int i = 0; i < 6; i++) {
                    const float xs = xr[32 * i];
                    const u64 xx = pk2(xs, xs);
                    a0 = ffma2(xx, gw2[i][0], a0);
                    a1 = ffma2(xx, gw2[i][1], a1);
                    a2 = ffma2(xx, gw2[i][2], a2);
                    a3 = ffma2(xx, gw2[i][3], a3);
                }
                float v0, v1, v2, v3, v4, v5, v6, v7;
                upk2(a0, v0, v1); upk2(a1, v2, v3); upk2(a2, v4, v5); upk2(a3, v6, v7);
                const float w0 = bfly(v0, v4, hi16, 16);
                const float w1 = bfly(v1, v5, hi16, 16);
                const float w2 = bfly(v2, v6, hi16, 16);
                const float w3 = bfly(v3, v7, hi16, 16);
                const float u0 = bfly(w0, w2, hi8, 8);
                const float u1 = bfly(w1, w3, hi8, 8);
                float z = bfly(u0, u1, hi4, 4);
                z += shx(z, 2);
                z += shx(z, 1);
                if ((lane & 3) == 0)
                    dpart[(r * 16 + 8 * c + (lane >> 2)) * 4 + g] = z;
            }
            BAR_SYNC(BID_DOWN_B, 256);

            // -- C: wait ring slot free, finalize stats + combine + relu --
            if (iter >= 2) BAR_SYNC(BID_EMPTY0 + buf, 512);
            {
                const float4* rp = reinterpret_cast<const float4*>(red_s + w * 16);
                const float4 f0 = rp[0], f1 = rp[1], f2 = rp[2], f3 = rp[3];
                const float s = ((f0.x + f0.z) + (f1.x + f1.z)) + ((f2.x + f2.z) + (f3.x + f3.z));
                const float q = ((f0.y + f0.w) + (f1.y + f1.w)) + ((f2.y + f2.w) + (f3.y + f3.w));
                const float mean = s * (1.0f / D_MODEL);
                const float var  = q * (1.0f / D_MODEL) - mean * mean;
                const float rstd = rsqrtf(var + 1e-5f);
                if (lane < 16) {
                    const float4 p4 = reinterpret_cast<const float4*>(dpart)[w * 16 + lane];
                    const float P = (p4.x + p4.y) + (p4.z + p4.w);
                    const float dv = rstd * (P - mean * G_s[lane]) + Cb_s[lane];
                    down_f[buf][w * 16 + lane] = fmaxf(dv, 0.0f);
                }
            }
            BAR_ARRIVE(BID_FULL0 + buf, 512);
            BAR_SYNC(BID_DOWN_A, 256);   // red_s/dpart reads done before next A/B

            b = nb; iter++;
        }
    } else {
        // ======================== UP role (warps 8-15) ========================
        const int tu = t - 256;
        // up weights: thread owns cols d = tu + 256j (j<3); all 8 k-pairs
        u64 wu2[3][8];
        float buj[3];
#pragma unroll
        for (int j = 0; j < 3; j++) {
            const int d = tu + 256 * j;
            buj[j] = bu[d];
#pragma unroll
            for (int p = 0; p < 8; p++)
                wu2[j][p] = pk2(wu[(2 * p) * D_MODEL + d], wu[(2 * p + 1) * D_MODEL + d]);
        }

        int b = blockIdx.x, iter = 0;
        float xr[RB][3];   // residual (global re-read, L2-hot)
        {
            const int rbase = b * RB;
#pragma unroll
            for (int r = 0; r < RB; r++)
#pragma unroll
                for (int j = 0; j < 3; j++)
                    xr[r][j] = x[(rbase + r) * D_MODEL + tu + 256 * j];
        }

        while (b < NBATCH) {
            const int buf   = iter & 1;
            const int rbase = b * RB;

            BAR_SYNC(BID_FULL0 + buf, 512);   // down_f[buf] ready

#pragma unroll
            for (int r = 0; r < RB; r++) {
                const float4 d0 = reinterpret_cast<const float4*>(down_f[buf])[r * 4 + 0];
                const float4 d1 = reinterpret_cast<const float4*>(down_f[buf])[r * 4 + 1];
                const float4 d2 = reinterpret_cast<const float4*>(down_f[buf])[r * 4 + 2];
                const float4 d3 = reinterpret_cast<const float4*>(down_f[buf])[r * 4 + 3];
                u64 dn[8];
                dn[0] = pk2(d0.x, d0.y); dn[1] = pk2(d0.z, d0.w);
                dn[2] = pk2(d1.x, d1.y); dn[3] = pk2(d1.z, d1.w);
                dn[4] = pk2(d2.x, d2.y); dn[5] = pk2(d2.z, d2.w);
                dn[6] = pk2(d3.x, d3.y); dn[7] = pk2(d3.z, d3.w);
#pragma unroll
                for (int j = 0; j < 3; j++) {
                    u64 u0 = 0ull, u1 = 0ull;
#pragma unroll
                    for (int p = 0; p < 8; p += 2) {
                        u0 = ffma2(dn[p],     wu2[j][p],     u0);
                        u1 = ffma2(dn[p + 1], wu2[j][p + 1], u1);
                    }
                    float f0, f1, f2, f3;
                    upk2(u0, f0, f1); upk2(u1, f2, f3);
                    const float up = (f0 + f1) + (f2 + f3);
                    out[(rbase + r) * D_MODEL + tu + 256 * j] = fmaf(0.1f, up + buj[j], xr[r][j]);
                }
            }
            BAR_ARRIVE(BID_EMPTY0 + buf, 512);   // ring slot free

            b += GRID; iter++;
            if (b < NBATCH) {                    // prefetch next residual
#pragma unroll
                for (int r = 0; r < RB; r++)
#pragma unroll
                    for (int j = 0; j < 3; j++)
                        xr[r][j] = x[(b * RB + r) * D_MODEL + tu + 256 * j];
            }
        }
    }
}

extern "C" void kernel_launch(void* const* d_in, const int* in_sizes, int n_in,
                              void* d_out, int out_size)
{
    const float* x    = (const float*)d_in[0];
    const float* ln_g = (const float*)d_in[1];
    const float* ln_b = (const float*)d_in[2];
    const float* wd   = (const float*)d_in[3];
    const float* bd   = (const float*)d_in[4];
    const float* wu   = (const float*)d_in[5];
    const float* bu   = (const float*)d_in[6];
    float* out = (float*)d_out;

    adapter_fused_kernel<<<GRID, NTHREADS>>>(x, ln_g, ln_b, wd, bd, wu, bu, out);
}

// round 10
// speedup vs baseline: 2.2016x; 1.0509x over previous
#include <cuda_runtime.h>
#include <cuda_bf16.h>
#include <cstdint>

// Fused adapter: out = x + 0.1f * ( relu( LN(x) @ Wd + bd ) @ Wu + bu )
// x: [32768, 768] fp32.  Wd: [768,16], Wu: [16,768].
//
// R8 (fixed): inverted warp-specialized pipeline, x read from global ONCE.
//   up warps (8-15): prefetch x -> stage x_s[buf] + LN stats -> (later)
//                    combine+relu -> up-proj + residual(from x_s) + store
//   down warps (0-7): single phase: sync XF -> folded down-proj -> arrive DPF
// 2-deep rings on x_s/red_s/dpart/down_f; one wait point per role per batch.
// LN folded into down-proj (R6): down_k = rstd*(dot(x,gw_k) - mean*G_k)+C_k.

#define D_MODEL  768
#define NROWS    32768
#define NTHREADS 512
#define RB       8
#define GRID     152
#define NBATCH   (NROWS / RB)   // 4096

// named barrier ids (0 reserved for __syncthreads)
#define B_XF0   1   // x_s[buf] staged: up arrives, down syncs (count 512)
#define B_DPF0  3   // dpart[buf] full: down arrives, up syncs (count 512)
#define B_UPI   5   // up-internal (count 256)

#define BAR_SYNC(id, n)   asm volatile("bar.sync %0, %1;"   :: "r"(id), "r"(n) : "memory")
#define BAR_ARRIVE(id, n) asm volatile("bar.arrive %0, %1;" :: "r"(id), "r"(n) : "memory")

// smem layout (floats)
#define OFF_X     0          // 2 * 6144
#define OFF_RED   12288      // 2 * 128
#define OFF_DP    12544      // 2 * 512
#define OFF_DNF   13568      // 2 * 128
#define OFF_G     13824      // 16
#define OFF_CB    13840      // 16
#define SMEM_FLOATS 13856
#define SMEM_BYTES  (SMEM_FLOATS * 4)

typedef unsigned long long u64;

__device__ __forceinline__ u64 pk2(float x, float y) {
    u64 r; asm("mov.b64 %0,{%1,%2};" : "=l"(r) : "f"(x), "f"(y)); return r;
}
__device__ __forceinline__ void upk2(u64 v, float& x, float& y) {
    asm("mov.b64 {%0,%1},%2;" : "=f"(x), "=f"(y) : "l"(v));
}
__device__ __forceinline__ u64 ffma2(u64 a, u64 b, u64 c) {
    u64 r; asm("fma.rn.f32x2 %0,%1,%2,%3;" : "=l"(r) : "l"(a), "l"(b), "l"(c)); return r;
}
__device__ __forceinline__ float shx(float v, int off) {
    return __shfl_xor_sync(0xFFFFFFFFu, v, off);
}
// Convergent pair-combine: ONE unconditional shuffle, operands selected first.
__device__ __forceinline__ float bfly(float a, float b, bool hi, int off) {
    const float keep = hi ? b : a;
    const float send = hi ? a : b;
    return keep + shx(send, off);
}

__global__ __launch_bounds__(NTHREADS, 1)
void adapter_fused_kernel(const float* __restrict__ x,
                          const float* __restrict__ ln_g,
                          const float* __restrict__ ln_b,
                          const float* __restrict__ wd,   // [768][16]
                          const float* __restrict__ bd,   // [16]
                          const float* __restrict__ wu,   // [16][768]
                          const float* __restrict__ bu,   // [768]
                          float* __restrict__ out)
{
    extern __shared__ __align__(16) float sm[];
    float* x_s   = sm + OFF_X;     // [2][RB*768]
    float* red_s = sm + OFF_RED;   // [2][RB*16]
    float* dpart = sm + OFF_DP;    // [2][RB*16*4]
    float* dnf   = sm + OFF_DNF;   // [2][RB*16]
    float* G_s   = sm + OFF_G;
    float* Cb_s  = sm + OFF_CB;

    const int t    = threadIdx.x;
    const int lane = t & 31;
    const bool hi16 = (lane & 16) != 0;
    const bool hi8  = (lane & 8)  != 0;
    const bool hi4  = (lane & 4)  != 0;
    const bool hi2  = (lane & 2)  != 0;

    // ===== init: G_k = sum gamma*Wd[:,k], Cb_k = sum beta*Wd[:,k] + bd =====
    if (t < 16) { G_s[t] = 0.0f; Cb_s[t] = bd[t]; }
    __syncthreads();
    if (t < 256) {
        float pg[16], pb[16];
#pragma unroll
        for (int k = 0; k < 16; k++) { pg[k] = 0.0f; pb[k] = 0.0f; }
#pragma unroll
        for (int j = 0; j < 3; j++) {
            const int d = t + 256 * j;
            const float gd = ln_g[d], bdv = ln_b[d];
#pragma unroll
            for (int k = 0; k < 16; k++) {
                const float wv = wd[d * 16 + k];
                pg[k] = fmaf(gd,  wv, pg[k]);
                pb[k] = fmaf(bdv, wv, pb[k]);
            }
        }
#pragma unroll
        for (int which = 0; which < 2; which++) {
            float* v = which ? pb : pg;
            float a8[8], b4[4], c2[2];
#pragma unroll
            for (int j = 0; j < 8; j++) a8[j] = bfly(v[j], v[j + 8], hi16, 16);
#pragma unroll
            for (int j = 0; j < 4; j++) b4[j] = bfly(a8[j], a8[j + 4], hi8, 8);
#pragma unroll
            for (int j = 0; j < 2; j++) c2[j] = bfly(b4[j], b4[j + 2], hi4, 4);
            float z = bfly(c2[0], c2[1], hi2, 2);
            z += shx(z, 1);
            if (!(lane & 1)) {
                if (which) atomicAdd(&Cb_s[lane >> 1], z);
                else       atomicAdd(&G_s[lane >> 1], z);
            }
        }
    }
    __syncthreads();   // G/Cb visible to everyone before pipeline starts

    if (t < 256) {
        // ===================== DOWN role (warps 0-7) =====================
        const int w = t >> 5;
        const int c = w & 1;        // k-chunk
        const int g = w >> 1;       // d-group of 192
        // gamma-folded down weights: lane owns d = 192g + 32i + lane (i<6)
        u64 gw2[6][4];
#pragma unroll
        for (int i = 0; i < 6; i++) {
            const int d = 192 * g + 32 * i + lane;
            const float gd = ln_g[d];
#pragma unroll
            for (int p = 0; p < 4; p++) {
                const float2 v = *reinterpret_cast<const float2*>(wd + d * 16 + 8 * c + 2 * p);
                gw2[i][p] = pk2(gd * v.x, gd * v.y);
            }
        }

        int b = blockIdx.x, s = 0;
        while (b < NBATCH) {
            const int buf = s & 1;
            BAR_SYNC(B_XF0 + buf, NTHREADS);
            const float* xb = x_s + buf * (RB * D_MODEL);
            float* dp = dpart + buf * (RB * 64);
#pragma unroll
            for (int r = 0; r < RB; r++) {
                u64 a0 = 0ull, a1 = 0ull, a2 = 0ull, a3 = 0ull;
                const float* xr = xb + r * D_MODEL + 192 * g + lane;
#pragma unroll
                for (int i = 0; i < 6; i++) {
                    const float xs = xr[32 * i];
                    const u64 xx = pk2(xs, xs);
                    a0 = ffma2(xx, gw2[i][0], a0);
                    a1 = ffma2(xx, gw2[i][1], a1);
                    a2 = ffma2(xx, gw2[i][2], a2);
                    a3 = ffma2(xx, gw2[i][3], a3);
                }
                float v0, v1, v2, v3, v4, v5, v6, v7;
                upk2(a0, v0, v1); upk2(a1, v2, v3); upk2(a2, v4, v5); upk2(a3, v6, v7);
                const float w0 = bfly(v0, v4, hi16, 16);
                const float w1 = bfly(v1, v5, hi16, 16);
                const float w2 = bfly(v2, v6, hi16, 16);
                const float w3 = bfly(v3, v7, hi16, 16);
                const float u0 = bfly(w0, w2, hi8, 8);
                const float u1 = bfly(w1, w3, hi8, 8);
                float z = bfly(u0, u1, hi4, 4);
                z += shx(z, 2);
                z += shx(z, 1);
                if ((lane & 3) == 0)
                    dp[(r * 16 + 8 * c + (lane >> 2)) * 4 + g] = z;
            }
            BAR_ARRIVE(B_DPF0 + buf, NTHREADS);
            b += GRID; s++;
        }
    } else {
        // ====================== UP role (warps 8-15) ======================
        const int tu = t - 256;
        const int cw = tu >> 5;       // 0..7 (combine row; NOT shadowing wu!)
        // up weights
        u64 wu2[3][8];
        float buj[3];
#pragma unroll
        for (int j = 0; j < 3; j++) {
            const int d = tu + 256 * j;
            buj[j] = bu[d];
#pragma unroll
            for (int p = 0; p < 8; p++)
                wu2[j][p] = pk2(wu[(2 * p) * D_MODEL + d], wu[(2 * p + 1) * D_MODEL + d]);
        }

        int b = blockIdx.x, s = 0;
        float xr[RB][3];

        // stage batch (held in xr) into buffer `buf` + LN stats
        auto stage = [&](int buf) {
            float* xd = x_s + buf * (RB * D_MODEL);
            float* rd = red_s + buf * (RB * 16);
#pragma unroll
            for (int r = 0; r < RB; r++) {
                xd[r * D_MODEL + tu]       = xr[r][0];
                xd[r * D_MODEL + tu + 256] = xr[r][1];
                xd[r * D_MODEL + tu + 512] = xr[r][2];
                float ss = (xr[r][0] + xr[r][1]) + xr[r][2];
                float qq = fmaf(xr[r][0], xr[r][0],
                           fmaf(xr[r][1], xr[r][1], xr[r][2] * xr[r][2]));
                float m = bfly(ss, qq, hi16, 16);
                m += shx(m, 8); m += shx(m, 4); m += shx(m, 2); m += shx(m, 1);
                if ((lane & 15) == 0)
                    rd[r * 16 + 2 * cw + (lane >> 4)] = m;
            }
        };
        auto loadxr = [&](int bb) {
#pragma unroll
            for (int r = 0; r < RB; r++)
#pragma unroll
                for (int j = 0; j < 3; j++)
                    xr[r][j] = x[(bb * RB + r) * D_MODEL + tu + 256 * j];
        };

        // prologue: stage batch b into buf 0
        loadxr(b);
        stage(0);
        BAR_ARRIVE(B_XF0, NTHREADS);
        if (b + GRID < NBATCH) loadxr(b + GRID);   // prefetch next (hidden)

        while (b < NBATCH) {
            const int bn   = b + GRID;
            const int bufc = s & 1;
            const int bufn = bufc ^ 1;

            if (bn < NBATCH) {
                stage(bufn);                        // consumes xr loaded 1 iter ago
                BAR_ARRIVE(B_XF0 + bufn, NTHREADS);
                if (bn + GRID < NBATCH) loadxr(bn + GRID);   // prefetch
            }

            BAR_SYNC(B_DPF0 + bufc, NTHREADS);      // down finished proj(b)

            // -- C: warp cw = row cw; finalize stats + combine + relu --
            {
                const float* rd = red_s + bufc * (RB * 16);
                const float4* rp = reinterpret_cast<const float4*>(rd + cw * 16);
                const float4 f0 = rp[0], f1 = rp[1], f2 = rp[2], f3 = rp[3];
                const float ss = ((f0.x + f0.z) + (f1.x + f1.z)) + ((f2.x + f2.z) + (f3.x + f3.z));
                const float qq = ((f0.y + f0.w) + (f1.y + f1.w)) + ((f2.y + f2.w) + (f3.y + f3.w));
                const float mean = ss * (1.0f / D_MODEL);
                const float var  = qq * (1.0f / D_MODEL) - mean * mean;
                const float rstd = rsqrtf(var + 1e-5f);
                if (lane < 16) {
                    const float* dp = dpart + bufc * (RB * 64);
                    const float4 p4 = reinterpret_cast<const float4*>(dp)[cw * 16 + lane];
                    const float P = (p4.x + p4.y) + (p4.z + p4.w);
                    const float dv = rstd * (P - mean * G_s[lane]) + Cb_s[lane];
                    dnf[bufc * (RB * 16) + cw * 16 + lane] = fmaxf(dv, 0.0f);
                }
            }
            BAR_SYNC(B_UPI, 256);                   // dnf[bufc] ready for all up warps

            // -- D: up-proj + scale + residual (from x_s[bufc]) + store --
            {
                const float* df = dnf + bufc * (RB * 16);
                const float* xb = x_s + bufc * (RB * D_MODEL);
                const int rbase = b * RB;
#pragma unroll
                for (int r = 0; r < RB; r++) {
                    const float4 d0 = reinterpret_cast<const float4*>(df)[r * 4 + 0];
                    const float4 d1 = reinterpret_cast<const float4*>(df)[r * 4 + 1];
                    const float4 d2 = reinterpret_cast<const float4*>(df)[r * 4 + 2];
                    const float4 d3 = reinterpret_cast<const float4*>(df)[r * 4 + 3];
                    u64 dn[8];
                    dn[0] = pk2(d0.x, d0.y); dn[1] = pk2(d0.z, d0.w);
                    dn[2] = pk2(d1.x, d1.y); dn[3] = pk2(d1.z, d1.w);
                    dn[4] = pk2(d2.x, d2.y); dn[5] = pk2(d2.z, d2.w);
                    dn[6] = pk2(d3.x, d3.y); dn[7] = pk2(d3.z, d3.w);
#pragma unroll
                    for (int j = 0; j < 3; j++) {
                        u64 u0 = 0ull, u1 = 0ull;
#pragma unroll
                        for (int p = 0; p < 8; p += 2) {
                            u0 = ffma2(dn[p],     wu2[j][p],     u0);
                            u1 = ffma2(dn[p + 1], wu2[j][p + 1], u1);
                        }
                        float f0, f1, f2, f3;
                        upk2(u0, f0, f1); upk2(u1, f2, f3);
                        const float up = (f0 + f1) + (f2 + f3);
                        const float res = xb[r * D_MODEL + tu + 256 * j];
                        out[(rbase + r) * D_MODEL + tu + 256 * j] = fmaf(0.1f, up + buj[j], res);
                    }
                }
            }
            b = bn; s++;
        }
    }
}

extern "C" void kernel_launch(void* const* d_in, const int* in_sizes, int n_in,
                              void* d_out, int out_size)
{
    const float* x    = (const float*)d_in[0];
    const float* ln_g = (const float*)d_in[1];
    const float* ln_b = (const float*)d_in[2];
    const float* wd   = (const float*)d_in[3];
    const float* bd   = (const float*)d_in[4];
    const float* wu   = (const float*)d_in[5];
    const float* bu   = (const float*)d_in[6];
    float* out = (float*)d_out;

    cudaFuncSetAttribute(adapter_fused_kernel,
                         cudaFuncAttributeMaxDynamicSharedMemorySize, SMEM_BYTES);
    adapter_fused_kernel<<<GRID, NTHREADS, SMEM_BYTES>>>(x, ln_g, ln_b, wd, bd, wu, bu, out);
}